// round 2
// baseline (speedup 1.0000x reference)
#include <cuda_runtime.h>
#include <cstdint>
#include <cstddef>

#define B_ 16
#define L_ 16384
#define C_ 256
#define NH 8
#define HD 32
#define FFN 512
#define EPS 1e-5f
#define SCALE_ATT 0.17677669529663687f

#define NCH 64      // chunks per batch
#define RPC 256     // rows per chunk
#define TR 64       // tile rows
#define NT 4        // tiles per chunk
#define KB 32       // k-tile depth
#define QKP_ST 260  // padded qkp row stride (bank-conflict avoidance)

typedef unsigned long long ull;

// ---------------- device scratch (static, no allocations) ----------------
__device__ float g_qkp[B_ * NH * C_];            // scale-folded q @ Wk per head
__device__ float g_qb[B_ * NH];                  // scale-folded q . bk per head
__device__ float g_pmax[B_ * NCH * NH];
__device__ float g_psum[B_ * NCH * NH];
__device__ float g_pctx[(size_t)B_ * NCH * NH * C_];   // 8 MB partial contexts

// ---------------- helpers ----------------
union F4 { float4 v; ull u[2]; };

__device__ __forceinline__ void ffma2(ull& d, ull a, ull b) {
    asm("fma.rn.f32x2 %0, %1, %2, %0;" : "+l"(d) : "l"(a), "l"(b));
}
__device__ __forceinline__ void mul2(ull& d, ull a) {
    asm("mul.rn.f32x2 %0, %0, %1;" : "+l"(d) : "l"(a));
}
__device__ __forceinline__ ull pack2(float x) {
    ull r; unsigned int u = __float_as_uint(x);
    asm("mov.b64 %0, {%1, %1};" : "=l"(r) : "r"(u));
    return r;
}
__device__ __forceinline__ float2 unpack2(ull v) {
    unsigned int lo, hi;
    asm("mov.b64 {%0, %1}, %2;" : "=r"(lo), "=r"(hi) : "l"(v));
    return make_float2(__uint_as_float(lo), __uint_as_float(hi));
}

// ============================================================
// K0: q = LN(query) @ W_q + b_q ; fold into qkp[b,h,c], qb[b,h]
// grid 16 (batch), 256 threads
// ============================================================
__global__ void k0_query(const float* __restrict__ query,
                         const float* __restrict__ W_q,  const float* __restrict__ b_q,
                         const float* __restrict__ W_kv, const float* __restrict__ b_kv,
                         const float* __restrict__ g_q,  const float* __restrict__ be_q)
{
    __shared__ float qn[C_], qs[C_], red[8], red2[8];
    const int b = blockIdx.x, t = threadIdx.x;

    float x = query[b * C_ + t];
    float s = x, s2 = x * x;
    #pragma unroll
    for (int o = 16; o >= 1; o >>= 1) {
        s  += __shfl_xor_sync(0xffffffffu, s,  o);
        s2 += __shfl_xor_sync(0xffffffffu, s2, o);
    }
    if ((t & 31) == 0) { red[t >> 5] = s; red2[t >> 5] = s2; }
    __syncthreads();
    float sum = 0.f, sumsq = 0.f;
    #pragma unroll
    for (int i = 0; i < 8; i++) { sum += red[i]; sumsq += red2[i]; }
    float mean = sum * (1.f / C_);
    float var  = sumsq * (1.f / C_) - mean * mean;
    float rs   = rsqrtf(var + EPS);
    qn[t] = (x - mean) * rs * g_q[t] + be_q[t];
    __syncthreads();

    float qj = b_q[t];
    for (int c = 0; c < C_; c++) qj += qn[c] * W_q[c * C_ + t];
    qs[t] = qj;
    __syncthreads();

    // qkp[b][h][c=t] = scale * sum_d qs[h*32+d] * W_kv[c][h*32+d]
    float a[NH];
    #pragma unroll
    for (int h = 0; h < NH; h++) a[h] = 0.f;
    const float* wrow = W_kv + (size_t)t * (2 * C_);
    #pragma unroll
    for (int h = 0; h < NH; h++) {
        float acc = 0.f;
        #pragma unroll 8
        for (int d = 0; d < HD; d++) acc += qs[h * HD + d] * wrow[h * HD + d];
        a[h] = acc;
    }
    #pragma unroll
    for (int h = 0; h < NH; h++)
        g_qkp[(b * NH + h) * C_ + t] = a[h] * SCALE_ATT;

    if (t < NH) {
        float qb = 0.f;
        #pragma unroll 8
        for (int d = 0; d < HD; d++) qb += qs[t * HD + d] * b_kv[t * HD + d];
        g_qb[b * NH + t] = qb * SCALE_ATT;
    }
}

// ============================================================
// K1: main fused kernel — m = LN(relu(mem@W_ip+b)), scores, online
// softmax, context accumulation. grid 1024 (b*64+chunk), 256 thr.
// ============================================================
struct SmemK1 {
    union {
        struct { float As[TR * KB]; float Bs[KB * C_]; } g;   // 40 KB
        float msm[TR * C_];                                    // 64 KB
    } u;
    float qkp[NH * QKP_ST];   // 8320 B
    float ctx[NH * C_];       // 8 KB
    float bip[C_], gip[C_], bei[C_];
    float ssm[NH * TR], wsm[NH * TR], iorsm[NH * TR];
    float qb[NH];
    float rmax[NH], rsum[NH], fsc[NH];
};

__global__ void __launch_bounds__(256, 2)
k1_main(const float* __restrict__ mem,  const float* __restrict__ ior,
        const float* __restrict__ W_ip, const float* __restrict__ b_ip,
        const float* __restrict__ g_ip, const float* __restrict__ be_ip)
{
    extern __shared__ char smraw[];
    SmemK1& S = *reinterpret_cast<SmemK1*>(smraw);
    const int t = threadIdx.x;
    const int b = blockIdx.x >> 6;
    const int ch = blockIdx.x & 63;
    const int trow = t >> 5, tcol = t & 31;

    // ---- per-block init ----
    for (int i = t; i < NH * C_; i += 256) {
        S.ctx[i] = 0.f;
        int h = i >> 8, c = i & 255;
        S.qkp[h * QKP_ST + c] = g_qkp[(b * NH + h) * C_ + c];
    }
    S.bip[t] = b_ip[t]; S.gip[t] = g_ip[t]; S.bei[t] = be_ip[t];
    if (t < NH) {
        S.qb[t]   = g_qb[b * NH + t];
        S.rmax[t] = -1e30f;
        S.rsum[t] = 0.f;
    }

    const float4* Am   = (const float4*)(mem + (size_t)(b * L_ + ch * RPC) * C_);
    const float4* Wip4 = (const float4*)W_ip;
    float4* As4 = (float4*)S.u.g.As;
    float4* Bs4 = (float4*)S.u.g.Bs;

    for (int tile = 0; tile < NT; tile++) {
        // ---- ior slab for this tile: [8 heads][64 rows] ----
        {
            const int base = ch * RPC + tile * TR;
            int i0 = t, i1 = t + 256;
            S.iorsm[i0] = ior[(b * NH + (i0 >> 6)) * L_ + base + (i0 & 63)];
            S.iorsm[i1] = ior[(b * NH + (i1 >> 6)) * L_ + base + (i1 & 63)];
        }

        // ---- GEMM: mtile[64,256] = mem_tile @ W_ip (f32x2) ----
        ull acc[8][4];
        #pragma unroll
        for (int r = 0; r < 8; r++)
            #pragma unroll
            for (int j = 0; j < 4; j++) acc[r][j] = 0ULL;

        for (int kt = 0; kt < C_ / KB; kt++) {
            __syncthreads();
            #pragma unroll
            for (int i = 0; i < 2; i++) {
                int f = t + i * 256;                    // f = row*8 + kv
                As4[f] = Am[(tile * TR + (f >> 3)) * 64 + kt * 8 + (f & 7)];
            }
            #pragma unroll
            for (int i = 0; i < 8; i++) {
                int f = t + i * 256;                    // f = kk*64 + c4
                Bs4[f] = Wip4[(kt * KB + (f >> 6)) * 64 + (f & 63)];
            }
            __syncthreads();
            #pragma unroll 8
            for (int kk = 0; kk < KB; kk++) {
                F4 b0, b1;
                b0.v = Bs4[kk * 64 + tcol];         // cols tcol*4 .. +3
                b1.v = Bs4[kk * 64 + 32 + tcol];    // cols 128+tcol*4 .. +3
                #pragma unroll
                for (int r = 0; r < 8; r++) {
                    ull ap = pack2(S.u.g.As[(trow * 8 + r) * KB + kk]);  // broadcast
                    ffma2(acc[r][0], ap, b0.u[0]);
                    ffma2(acc[r][1], ap, b0.u[1]);
                    ffma2(acc[r][2], ap, b1.u[0]);
                    ffma2(acc[r][3], ap, b1.u[1]);
                }
            }
        }
        __syncthreads();   // all As/Bs reads done; msm may overwrite union

        // ---- epilogue: bias + relu + LayerNorm -> msm ----
        {
            float bf[8], gf[8], ef[8];
            const float4* bip4 = (const float4*)S.bip;
            const float4* gip4 = (const float4*)S.gip;
            const float4* bei4 = (const float4*)S.bei;
            *(float4*)&bf[0] = bip4[tcol]; *(float4*)&bf[4] = bip4[32 + tcol];
            *(float4*)&gf[0] = gip4[tcol]; *(float4*)&gf[4] = gip4[32 + tcol];
            *(float4*)&ef[0] = bei4[tcol]; *(float4*)&ef[4] = bei4[32 + tcol];

            #pragma unroll
            for (int i = 0; i < 8; i++) {
                int row = trow * 8 + i;
                float v[8]; float2 p;
                p = unpack2(acc[i][0]); v[0] = p.x; v[1] = p.y;
                p = unpack2(acc[i][1]); v[2] = p.x; v[3] = p.y;
                p = unpack2(acc[i][2]); v[4] = p.x; v[5] = p.y;
                p = unpack2(acc[i][3]); v[6] = p.x; v[7] = p.y;
                float sum = 0.f, sumsq = 0.f;
                #pragma unroll
                for (int j = 0; j < 8; j++) {
                    float x = fmaxf(v[j] + bf[j], 0.f);
                    v[j] = x; sum += x; sumsq += x * x;
                }
                #pragma unroll
                for (int o = 16; o >= 1; o >>= 1) {
                    sum   += __shfl_xor_sync(0xffffffffu, sum,   o);
                    sumsq += __shfl_xor_sync(0xffffffffu, sumsq, o);
                }
                float mean = sum * (1.f / C_);
                float var  = sumsq * (1.f / C_) - mean * mean;
                float rs   = rsqrtf(var + EPS);
                float o0[4], o1[4];
                #pragma unroll
                for (int j = 0; j < 4; j++) o0[j] = (v[j] - mean) * rs * gf[j] + ef[j];
                #pragma unroll
                for (int j = 0; j < 4; j++) o1[j] = (v[4 + j] - mean) * rs * gf[4 + j] + ef[4 + j];
                float4* d = (float4*)&S.u.msm[row * C_];
                d[tcol]      = make_float4(o0[0], o0[1], o0[2], o0[3]);
                d[32 + tcol] = make_float4(o1[0], o1[1], o1[2], o1[3]);
            }
        }
        __syncthreads();

        // ---- scores: ssm[h][r] = (m_r . qkp_h + qb_h) * ior ----
        {
            const int h = t & 7, r0 = t >> 3;     // r0 in 0..31
            #pragma unroll
            for (int half = 0; half < 2; half++) {
                int r = r0 + half * 32;
                const float4* mr = (const float4*)&S.u.msm[r * C_];
                const float4* qr = (const float4*)&S.qkp[h * QKP_ST];
                float a = 0.f;
                #pragma unroll 8
                for (int c4 = 0; c4 < 64; c4++) {
                    float4 mv = mr[c4], qv = qr[c4];
                    a += mv.x * qv.x + mv.y * qv.y + mv.z * qv.z + mv.w * qv.w;
                }
                S.ssm[h * TR + r] = (a + S.qb[h]) * S.iorsm[h * TR + r];
            }
        }
        __syncthreads();

        // ---- online softmax update (warp w handles head w) ----
        {
            const int w = t >> 5, lane = t & 31;
            float s0 = S.ssm[w * TR + lane], s1 = S.ssm[w * TR + 32 + lane];
            float mx = fmaxf(s0, s1);
            #pragma unroll
            for (int o = 16; o >= 1; o >>= 1)
                mx = fmaxf(mx, __shfl_xor_sync(0xffffffffu, mx, o));
            float om = S.rmax[w];
            float nm = fmaxf(om, mx);
            float e0 = __expf(s0 - nm), e1 = __expf(s1 - nm);
            S.wsm[w * TR + lane]      = e0;
            S.wsm[w * TR + 32 + lane] = e1;
            float es = e0 + e1;
            #pragma unroll
            for (int o = 16; o >= 1; o >>= 1)
                es += __shfl_xor_sync(0xffffffffu, es, o);
            if (lane == 0) {
                float f = __expf(om - nm);
                S.fsc[w]  = f;
                S.rsum[w] = S.rsum[w] * f + es;
                S.rmax[w] = nm;
            }
        }
        __syncthreads();

        // ---- context accumulate: ctx[h][c] = ctx*f + sum_r w[r]*m[r][c] ----
        {
            const int h = t >> 5, c04 = (t & 31) * 2;   // float4 idx, cols (t&31)*8
            float4* ctx4 = (float4*)&S.ctx[h * C_];
            F4 c0u, c1u;
            c0u.v = ctx4[c04]; c1u.v = ctx4[c04 + 1];
            ull fp = pack2(S.fsc[h]);
            ull cx0 = c0u.u[0], cx1 = c0u.u[1], cx2 = c1u.u[0], cx3 = c1u.u[1];
            mul2(cx0, fp); mul2(cx1, fp); mul2(cx2, fp); mul2(cx3, fp);
            #pragma unroll 8
            for (int r = 0; r < TR; r++) {
                ull wp = pack2(S.wsm[h * TR + r]);
                const float4* mr = (const float4*)&S.u.msm[r * C_];
                F4 m0, m1; m0.v = mr[c04]; m1.v = mr[c04 + 1];
                ffma2(cx0, wp, m0.u[0]);
                ffma2(cx1, wp, m0.u[1]);
                ffma2(cx2, wp, m1.u[0]);
                ffma2(cx3, wp, m1.u[1]);
            }
            F4 o0, o1;
            o0.u[0] = cx0; o0.u[1] = cx1; o1.u[0] = cx2; o1.u[1] = cx3;
            ctx4[c04] = o0.v; ctx4[c04 + 1] = o1.v;
        }
        // loop-entry syncthreads guards the msm/As/Bs union for next tile
    }

    __syncthreads();
    // ---- write partials ----
    for (int i = t; i < NH * C_; i += 256)
        g_pctx[(size_t)blockIdx.x * (NH * C_) + i] = S.ctx[i];
    if (t < NH) {
        g_pmax[blockIdx.x * NH + t] = S.rmax[t];
        g_psum[blockIdx.x * NH + t] = S.rsum[t];
    }
}

// ============================================================
// K2: combine partials, V-projection, residual, LN, FFN (exact GELU)
// grid 16 (batch), 256 threads
// ============================================================
__global__ void k2_final(const float* __restrict__ query,
                         const float* __restrict__ W_kv, const float* __restrict__ b_kv,
                         const float* __restrict__ g_f,  const float* __restrict__ be_f,
                         const float* __restrict__ W1,   const float* __restrict__ b1,
                         const float* __restrict__ W2,   const float* __restrict__ b2,
                         float* __restrict__ out)
{
    __shared__ float pm[NCH * NH], ps[NCH * NH], gm[NH], gs[NH];
    __shared__ float ctxn[NH * C_];
    __shared__ float xs[C_], hs[C_], us[FFN];
    __shared__ float red[8], red2[8];
    const int b = blockIdx.x, t = threadIdx.x;

    for (int i = t; i < NCH * NH; i += 256) {
        pm[i] = g_pmax[b * NCH * NH + i];
        ps[i] = g_psum[b * NCH * NH + i];
    }
    __syncthreads();

    // global max / sum per head (warp w = head w; lanes cover 2 chunks each)
    {
        const int w = t >> 5, lane = t & 31;
        float a = pm[lane * NH + w], c = pm[(lane + 32) * NH + w];
        float mx = fmaxf(a, c);
        #pragma unroll
        for (int o = 16; o >= 1; o >>= 1)
            mx = fmaxf(mx, __shfl_xor_sync(0xffffffffu, mx, o));
        float sm = ps[lane * NH + w] * __expf(a - mx)
                 + ps[(lane + 32) * NH + w] * __expf(c - mx);
        #pragma unroll
        for (int o = 16; o >= 1; o >>= 1)
            sm += __shfl_xor_sync(0xffffffffu, sm, o);
        if (lane == 0) { gm[w] = mx; gs[w] = sm; }
    }
    __syncthreads();

    // combine contexts
    {
        const int h = t >> 5, c0 = (t & 31) * 8;
        float a[8];
        #pragma unroll
        for (int j = 0; j < 8; j++) a[j] = 0.f;
        for (int chh = 0; chh < NCH; chh++) {
            float f = __expf(pm[chh * NH + h] - gm[h]);
            const float4* p = (const float4*)&g_pctx[((size_t)(b * NCH + chh) * NH + h) * C_ + c0];
            float4 v0 = p[0], v1 = p[1];
            a[0] += f * v0.x; a[1] += f * v0.y; a[2] += f * v0.z; a[3] += f * v0.w;
            a[4] += f * v1.x; a[5] += f * v1.y; a[6] += f * v1.z; a[7] += f * v1.w;
        }
        float inv = 1.f / gs[h];
        #pragma unroll
        for (int j = 0; j < 8; j++) ctxn[h * C_ + c0 + j] = a[j] * inv;
    }
    __syncthreads();

    // V projection + residual + LN
    {
        const int h = t >> 5;
        float o = b_kv[C_ + t];
        for (int c = 0; c < C_; c++) o += ctxn[h * C_ + c] * W_kv[c * (2 * C_) + C_ + t];
        float x = o + query[b * C_ + t];
        xs[t] = x;
        float s = x, s2 = x * x;
        #pragma unroll
        for (int o2 = 16; o2 >= 1; o2 >>= 1) {
            s  += __shfl_xor_sync(0xffffffffu, s,  o2);
            s2 += __shfl_xor_sync(0xffffffffu, s2, o2);
        }
        if ((t & 31) == 0) { red[t >> 5] = s; red2[t >> 5] = s2; }
        __syncthreads();
        float sum = 0.f, sumsq = 0.f;
        #pragma unroll
        for (int i = 0; i < 8; i++) { sum += red[i]; sumsq += red2[i]; }
        float mean = sum * (1.f / C_);
        float var  = sumsq * (1.f / C_) - mean * mean;
        float rs   = rsqrtf(var + EPS);
        hs[t] = (x - mean) * rs * g_f[t] + be_f[t];
    }
    __syncthreads();

    // FFN layer 1 + exact GELU
    for (int f = t; f < FFN; f += 256) {
        float u = b1[f];
        for (int c = 0; c < C_; c++) u += hs[c] * W1[c * FFN + f];
        us[f] = 0.5f * u * (1.f + erff(u * 0.70710678118654752f));
    }
    __syncthreads();

    // FFN layer 2 + residual
    {
        float y = b2[t];
        for (int f = 0; f < FFN; f++) y += us[f] * W2[f * C_ + t];
        out[b * C_ + t] = xs[t] + y;
    }
}

// ============================================================
extern "C" void kernel_launch(void* const* d_in, const int* in_sizes, int n_in,
                              void* d_out, int out_size)
{
    const float* query = (const float*)d_in[0];
    const float* mem   = (const float*)d_in[1];
    const float* ior   = (const float*)d_in[2];
    const float* W_ip  = (const float*)d_in[3];
    const float* b_ip  = (const float*)d_in[4];
    const float* g_ip  = (const float*)d_in[5];
    const float* be_ip = (const float*)d_in[6];
    const float* W_q   = (const float*)d_in[7];
    const float* b_q   = (const float*)d_in[8];
    const float* W_kv  = (const float*)d_in[9];
    const float* b_kv  = (const float*)d_in[10];
    const float* g_q   = (const float*)d_in[11];
    const float* be_q  = (const float*)d_in[12];
    const float* g_f   = (const float*)d_in[13];
    const float* be_f  = (const float*)d_in[14];
    const float* W1    = (const float*)d_in[15];
    const float* b1    = (const float*)d_in[16];
    const float* W2    = (const float*)d_in[17];
    const float* b2    = (const float*)d_in[18];
    float* out = (float*)d_out;

    const int smem = (int)sizeof(SmemK1);
    cudaFuncSetAttribute(k1_main, cudaFuncAttributeMaxDynamicSharedMemorySize, smem);

    k0_query<<<B_, 256>>>(query, W_q, b_q, W_kv, b_kv, g_q, be_q);
    k1_main<<<B_ * NCH, 256, smem>>>(mem, ior, W_ip, b_ip, g_ip, be_ip);
    k2_final<<<B_, 256>>>(query, W_kv, b_kv, g_f, be_f, W1, b1, W2, b2, out);
}